// round 13
// baseline (speedup 1.0000x reference)
#include <cuda_runtime.h>
#include <cstdint>

#define NN    2000
#define D     16
#define TILE  8192           // B*T*D = 8*64*16
#define BR    3
#define MAXPAD 16384         // >= n3 + 3*NN

// Scratch (device globals: no allocation allowed in kernel_launch)
__device__ float g_y2[1800 * TILE];   // fc(h2), consumed by gather
__device__ int   g_counts[NN];
__device__ int   g_off[NN];           // padded exclusive offsets (multiples of 4)
__device__ int   g_perm[MAXPAD];      // leaf index, ~first for pad slots
__device__ int   g_pad_total;
__device__ __align__(16) int   g_pe[MAXPAD];        // pe3[perm[k]], dense
__device__ __align__(16) float g_scl[MAXPAD * 16];  // scales (0 for pad), dense

// One block: counts, padded exclusive-scan offsets, scatter permutation, pad fill.
__global__ void __launch_bounds__(1024) prep_kernel(const int* __restrict__ cn3, int n3) {
    __shared__ int sCnt[2048];
    __shared__ int sScan[2048];
    const int t = threadIdx.x;

    sCnt[t] = 0; sCnt[t + 1024] = 0;
    __syncthreads();
    for (int j = t; j < n3; j += 1024) atomicAdd(&sCnt[cn3[j]], 1);
    __syncthreads();

    // exclusive scan of PADDED counts (pad each to multiple of 4)
    sScan[t]        = (t == 0) ? 0 : ((sCnt[t - 1] + 3) & ~3);
    sScan[t + 1024] = (sCnt[t + 1023] + 3) & ~3;
    __syncthreads();
    for (int d = 1; d < 2048; d <<= 1) {
        int a = sScan[t]        + ((t >= d)        ? sScan[t - d]        : 0);
        int b = sScan[t + 1024] + ((t + 1024 >= d) ? sScan[t + 1024 - d] : 0);
        __syncthreads();
        sScan[t] = a; sScan[t + 1024] = b;
        __syncthreads();
    }

    if (t < NN)        { g_counts[t] = sCnt[t];           g_off[t] = sScan[t]; }
    if (t + 1024 < NN) { g_counts[t+1024] = sCnt[t+1024]; g_off[t+1024] = sScan[t+1024]; }
    if (t == 0) g_pad_total = sScan[NN - 1] + ((sCnt[NN - 1] + 3) & ~3);

    sCnt[t] = 0; sCnt[t + 1024] = 0;
    __syncthreads();
    for (int j = t; j < n3; j += 1024) {
        int c = cn3[j];
        int pos = atomicAdd(&sCnt[c], 1);
        g_perm[sScan[c] + pos] = j;
    }
    __syncthreads();

    // pad fill: duplicate first leaf index, flagged with ~ (scale will be 0)
    for (int i = t; i < NN; i += 1024) {
        int c = g_counts[i];
        if (c == 0) continue;
        int off = g_off[i];
        int pc = (c + 3) & ~3;
        int first = g_perm[off];
        for (int k = c; k < pc; k++) g_perm[off + k] = ~first;
    }
}

// Grid-parallel: resolve all gather-side indirection into dense arrays.
__global__ void __launch_bounds__(256) scale_fill_kernel(
    const float* __restrict__ A, const int* __restrict__ pe3,
    const int* __restrict__ pn3, const int* __restrict__ cn3)
{
    int idx = blockIdx.x * blockDim.x + threadIdx.x;     // over pad_total*16
    if (idx >= g_pad_total * 16) return;
    int k = idx >> 4, f = idx & 15;
    int j = g_perm[k];
    bool pad = (j < 0);
    if (pad) j = ~j;
    g_scl[idx] = pad ? 0.f
                     : A[(size_t)f * NN * NN + (size_t)pn3[j] * NN + (size_t)cn3[j]];
    if (f == 0) g_pe[k] = pe3[j];
}

// fc over 16 features with 4 threads/row: each thread owns 4 contiguous features
// (part = lane&3). Full 16-vector gathered via 3-shfl butterfly within the 4-lane group.
__device__ __forceinline__ void fc4(const float h[4], int part,
                                    const float* __restrict__ sW,
                                    const float* __restrict__ sb, float y[4]) {
    float g1[4], g2[4], g3[4];
    #pragma unroll
    for (int i = 0; i < 4; i++) g1[i] = __shfl_xor_sync(0xffffffffu, h[i], 1);
    #pragma unroll
    for (int i = 0; i < 4; i++) g2[i] = __shfl_xor_sync(0xffffffffu, h[i], 2);
    #pragma unroll
    for (int i = 0; i < 4; i++) g3[i] = __shfl_xor_sync(0xffffffffu, g1[i], 2);
    const int p0 = part * 4;
    const int p1 = (part ^ 1) * 4;
    const int p2 = (part ^ 2) * 4;
    const int p3 = (part ^ 3) * 4;
    #pragma unroll
    for (int f = 0; f < 4; f++) {
        const float* wr = sW + (p0 + f) * 16;
        float acc = sb[p0 + f];
        #pragma unroll
        for (int i = 0; i < 4; i++) acc = fmaf(h[i],  wr[p0 + i], acc);
        #pragma unroll
        for (int i = 0; i < 4; i++) acc = fmaf(g1[i], wr[p1 + i], acc);
        #pragma unroll
        for (int i = 0; i < 4; i++) acc = fmaf(g2[i], wr[p2 + i], acc);
        #pragma unroll
        for (int i = 0; i < 4; i++) acc = fmaf(g3[i], wr[p3 + i], acc);
        y[f] = acc;
    }
}

// Fused levels 0+1: one block per (root, eighth-tile). 256 threads, 4/row (64 rows).
__global__ void __launch_bounds__(256) tree_kernel(
    const float* __restrict__ x, const float* __restrict__ A,
    const float* __restrict__ W, const float* __restrict__ bias,
    const int* __restrict__ root_ids,
    const int* __restrict__ pn1, const int* __restrict__ cn1,
    const int* __restrict__ pn2, const int* __restrict__ cn2)
{
    __shared__ float sW[256];
    __shared__ float sb16[16];
    __shared__ float sS1[3][16];
    __shared__ float sS2[9][16];
    __shared__ int   sCn1[3];
    __shared__ int   sCn2[9];

    const int rp  = blockIdx.x >> 3;
    const int oct = blockIdx.x & 7;
    const int t   = threadIdx.x;

    sW[t] = W[t];
    if (t < 16) sb16[t] = bias[t];
    if (t >= 32 && t < 32 + 48) {            // distinct warps for S1/S2 loads
        int u = t - 32;
        int c = u >> 4, f = u & 15;
        int j1 = rp * 3 + c;
        int pnj = pn1[j1], cnj = cn1[j1];
        sS1[c][f] = A[(size_t)f * NN * NN + (size_t)pnj * NN + (size_t)cnj];
        if (f == 0) sCn1[c] = cnj;
    } else if (t >= 96 && t < 96 + 144) {
        int u = t - 96;
        int c = u >> 4, f = u & 15;
        int j2 = rp * 9 + c;
        int pnj = pn2[j2], cnj = cn2[j2];
        sS2[c][f] = A[(size_t)f * NN * NN + (size_t)pnj * NN + (size_t)cnj];
        if (f == 0) sCn2[c] = cnj;
    }

    const int part = t & 3;
    const int row  = oct * 64 + (t >> 2);
    const size_t roff = (size_t)row * D + part * 4;
    const int fb = part * 4;

    float h[4];
    {
        float4 v = *(const float4*)(x + (size_t)root_ids[rp] * TILE + roff);
        h[0]=v.x; h[1]=v.y; h[2]=v.z; h[3]=v.w;
    }
    __syncthreads();

    float yp[4];
    fc4(h, part, sW, sb16, yp);          // fc(root)

    #pragma unroll 1
    for (int c1 = 0; c1 < 3; c1++) {
        float h1[4];
        {
            float4 v = *(const float4*)(x + (size_t)sCn1[c1] * TILE + roff);
            const float* s1v = &sS1[c1][fb];
            h1[0]=fmaf(yp[0],s1v[0],v.x);
            h1[1]=fmaf(yp[1],s1v[1],v.y);
            h1[2]=fmaf(yp[2],s1v[2],v.z);
            h1[3]=fmaf(yp[3],s1v[3],v.w);
        }
        float y1[4];
        fc4(h1, part, sW, sb16, y1);     // fc(h1) feeds level-2 children

        #pragma unroll
        for (int c2 = 0; c2 < 3; c2++) {
            const int cc = c1 * 3 + c2;
            float h2[4];
            {
                float4 v = *(const float4*)(x + (size_t)sCn2[cc] * TILE + roff);
                const float* s2v = &sS2[cc][fb];
                h2[0]=fmaf(y1[0],s2v[0],v.x);
                h2[1]=fmaf(y1[1],s2v[1],v.y);
                h2[2]=fmaf(y1[2],s2v[2],v.z);
                h2[3]=fmaf(y1[3],s2v[3],v.w);
            }
            float y2v[4];
            fc4(h2, part, sW, sb16, y2v); // store fc(h2) for gather

            *(float4*)(g_y2 + ((size_t)rp * 9 + cc) * TILE + roff) =
                make_float4(y2v[0], y2v[1], y2v[2], y2v[3]);
        }
    }
}

// Eighth-tile blocks, 128 threads, STRIPED LDG.32 accesses.
// Thread t owns elements {j*128 + t : j=0..7} of its 1024-float slice, so every
// load instruction is one 128B line (1.0 cyc/wf, no within-LDG replays).
// Element feature = t & 15 (constant per lane) -> one scalar scale per leaf.
__global__ void __launch_bounds__(128) gather_kernel(
    const float* __restrict__ x, float* __restrict__ out)
{
    const int node = blockIdx.x >> 3;
    const int oct  = blockIdx.x & 7;
    const int t    = threadIdx.x;

    const int cnt = g_counts[node];
    const size_t sbase = (size_t)node * TILE + (size_t)oct * 1024 + t;

    float xv[8];
    #pragma unroll
    for (int j = 0; j < 8; j++) xv[j] = __ldcs(x + sbase + j * 128);

    if (cnt > 0) {
        float acc[8];
        #pragma unroll
        for (int j = 0; j < 8; j++) acc[j] = 0.f;

        const int off  = g_off[node];        // multiple of 4
        const int pc   = (cnt + 3) & ~3;
        const int feat = t & 15;
        const size_t yoff = (size_t)oct * 1024 + t;

        for (int k = 0; k < pc; k += 4) {
            const int4 pe4 = *(const int4*)(g_pe + off + k);
            const float* y0 = g_y2 + (size_t)pe4.x * TILE + yoff;
            const float* y1 = g_y2 + (size_t)pe4.y * TILE + yoff;
            const float* y2 = g_y2 + (size_t)pe4.z * TILE + yoff;
            const float* y3 = g_y2 + (size_t)pe4.w * TILE + yoff;

            float a[8], b[8], c[8], d[8];
            #pragma unroll
            for (int j = 0; j < 8; j++) a[j] = y0[j * 128];
            #pragma unroll
            for (int j = 0; j < 8; j++) b[j] = y1[j * 128];
            #pragma unroll
            for (int j = 0; j < 8; j++) c[j] = y2[j * 128];
            #pragma unroll
            for (int j = 0; j < 8; j++) d[j] = y3[j * 128];

            const float s0 = g_scl[(size_t)(off + k + 0) * 16 + feat];
            const float s1 = g_scl[(size_t)(off + k + 1) * 16 + feat];
            const float s2 = g_scl[(size_t)(off + k + 2) * 16 + feat];
            const float s3 = g_scl[(size_t)(off + k + 3) * 16 + feat];

            #pragma unroll
            for (int j = 0; j < 8; j++) {
                acc[j] = fmaf(a[j], s0, acc[j]);
                acc[j] = fmaf(b[j], s1, acc[j]);
                acc[j] = fmaf(c[j], s2, acc[j]);
                acc[j] = fmaf(d[j], s3, acc[j]);
            }
        }
        const float inv = 1.0f / (float)cnt;
        #pragma unroll
        for (int j = 0; j < 8; j++) xv[j] = fmaf(acc[j], inv, xv[j]);
    }

    #pragma unroll
    for (int j = 0; j < 8; j++) __stcs(out + sbase + j * 128, xv[j]);
}

extern "C" void kernel_launch(void* const* d_in, const int* in_sizes, int n_in,
                              void* d_out, int out_size) {
    const float* x    = (const float*)d_in[0];
    const float* A    = (const float*)d_in[1];
    const float* W    = (const float*)d_in[2];
    const float* b    = (const float*)d_in[3];
    const int*   root = (const int*)d_in[4];
    const int*   pn1  = (const int*)d_in[6];
    const int*   cn1  = (const int*)d_in[7];
    const int*   pn2  = (const int*)d_in[9];
    const int*   cn2  = (const int*)d_in[10];
    const int*   pe3  = (const int*)d_in[11];
    const int*   pn3  = (const int*)d_in[12];
    const int*   cn3  = (const int*)d_in[13];
    float* out = (float*)d_out;

    const int n1 = in_sizes[5];    // 600
    const int n3 = in_sizes[11];   // 5400
    const int n_roots = n1 / BR;   // 200

    static cudaStream_t s_side = nullptr;
    static cudaEvent_t  ev_fork = nullptr, ev_join = nullptr;
    if (!s_side) {
        cudaStreamCreateWithFlags(&s_side, cudaStreamNonBlocking);
        cudaEventCreateWithFlags(&ev_fork, cudaEventDisableTiming);
        cudaEventCreateWithFlags(&ev_join, cudaEventDisableTiming);
    }

    // prep + scale resolve only feed gather; run them concurrently with tree_kernel.
    cudaEventRecord(ev_fork, 0);
    cudaStreamWaitEvent(s_side, ev_fork, 0);
    prep_kernel<<<1, 1024, 0, s_side>>>(cn3, n3);
    const int padmax = n3 + 3 * NN;
    scale_fill_kernel<<<(padmax * 16 + 255) / 256, 256, 0, s_side>>>(A, pe3, pn3, cn3);
    cudaEventRecord(ev_join, s_side);

    tree_kernel<<<8 * n_roots, 256>>>(x, A, W, b, root, pn1, cn1, pn2, cn2);

    cudaStreamWaitEvent(0, ev_join, 0);
    gather_kernel<<<8 * NN, 128>>>(x, out);
}